// round 7
// baseline (speedup 1.0000x reference)
#include <cuda_runtime.h>
#include <cstdint>

// diff[k] = (f[k-3] - f[k+2]) / 5 with zero-padding outside [0,n)
// change[k] = diff[k]^2 for k>=1, change[0] = 0
// out[k] = (1 - change[k]/S)^5 * f[k],  S = sum(change)

#define TPB 256
#define VPT 5                              // float4 vectors per thread
#define CHUNK_F (TPB * VPT * 4)            // 5120 floats per block
#define HALO_LO 4                          // tile loads [base-4, base+CHUNK_F+12)
#define HALO_HI 12
#define TILE_F (CHUNK_F + HALO_LO + HALO_HI)   // 5136 floats
#define TILE_BYTES (TILE_F * 4)                // 20544 bytes (16B multiple)
#define MAX_BLOCKS 16384
#define FULL 0xffffffffu

__device__ float g_part[MAX_BLOCKS];
__device__ float g_invS;

__device__ __forceinline__ uint32_t smem_u32(const void* p) {
    return (uint32_t)__cvta_generic_to_shared(p);
}

// ---------------------------------------------------------------- pass 1
__global__ void __launch_bounds__(TPB) k_pass1(const float* __restrict__ f, int n) {
    __shared__ alignas(128) float s[TILE_F];
    __shared__ alignas(8) unsigned long long mbar;

    const int tid  = threadIdx.x;
    const int bid  = blockIdx.x;
    const int lane = tid & 31;
    const int warp = tid >> 5;
    const int base = bid * CHUNK_F;
    const bool interior = (bid > 0) && (base + CHUNK_F + HALO_HI <= n);

    float acc = 0.0f;

    if (interior) {
        // ---- TMA bulk copy: one 20.5KB transfer replaces 1280 LDGs ----
        const uint32_t mb = smem_u32(&mbar);
        if (tid == 0) {
            asm volatile("mbarrier.init.shared.b64 [%0], %1;" :: "r"(mb), "r"(1) : "memory");
        }
        __syncthreads();
        if (tid == 0) {
            asm volatile("mbarrier.arrive.expect_tx.shared.b64 _, [%0], %1;"
                         :: "r"(mb), "r"((uint32_t)TILE_BYTES) : "memory");
            asm volatile(
                "cp.async.bulk.shared::cluster.global.mbarrier::complete_tx::bytes "
                "[%0], [%1], %2, [%3];"
                :: "r"(smem_u32(s)), "l"(f + base - HALO_LO),
                   "r"((uint32_t)TILE_BYTES), "r"(mb) : "memory");
        }
        // all threads wait (parity 0, acquire)
        {
            uint32_t done = 0;
            while (!done) {
                asm volatile(
                    "{\n\t.reg .pred p;\n\t"
                    "mbarrier.try_wait.parity.acquire.cta.shared::cta.b64 p, [%1], %2;\n\t"
                    "selp.b32 %0, 1, 0, p;\n\t}"
                    : "=r"(done) : "r"(mb), "r"(0u) : "memory");
            }
        }

        // ---- compute from smem (halo directly addressable) ----
        #pragma unroll
        for (int j = 0; j < VPT; j++) {
            const int idx = HALO_LO + j * (TPB * 4) + tid * 4;   // 16B-aligned
            float4 c = *reinterpret_cast<const float4*>(s + idx);
            float m3 = s[idx - 3];
            float m2 = s[idx - 2];
            float m1 = s[idx - 1];
            float p4 = s[idx + 4];
            float p5 = s[idx + 5];
            float d0 = (m3  - c.z) * 0.2f;
            float d1 = (m2  - c.w) * 0.2f;
            float d2 = (m1  - p4 ) * 0.2f;
            float d3 = (c.x - p5 ) * 0.2f;
            acc += d0 * d0 + d1 * d1 + d2 * d2 + d3 * d3;
        }
    } else {
        #pragma unroll
        for (int j = 0; j < VPT; j++) {
            const int v = base + j * (TPB * 4) + tid * 4;
            if (v + 3 < n) {
                float4 c = __ldg(reinterpret_cast<const float4*>(f + v));
                float m3 = (v >= 3)     ? __ldg(f + v - 3) : 0.0f;
                float m2 = (v >= 2)     ? __ldg(f + v - 2) : 0.0f;
                float m1 = (v >= 1)     ? __ldg(f + v - 1) : 0.0f;
                float p4 = (v + 4 < n)  ? __ldg(f + v + 4) : 0.0f;
                float p5 = (v + 5 < n)  ? __ldg(f + v + 5) : 0.0f;
                float d0 = (m3  - c.z) * 0.2f;
                float d1 = (m2  - c.w) * 0.2f;
                float d2 = (m1  - p4 ) * 0.2f;
                float d3 = (c.x - p5 ) * 0.2f;
                float c0 = (v == 0) ? 0.0f : d0 * d0;
                acc += c0 + d1 * d1 + d2 * d2 + d3 * d3;
            } else if (v < n) {
                for (int k = v; k < n; k++) {
                    float l = (k >= 3)    ? __ldg(f + k - 3) : 0.0f;
                    float r = (k + 2 < n) ? __ldg(f + k + 2) : 0.0f;
                    float d = (l - r) * 0.2f;
                    if (k != 0) acc += d * d;
                }
            }
        }
    }

    #pragma unroll
    for (int o = 16; o > 0; o >>= 1)
        acc += __shfl_down_sync(FULL, acc, o);

    __shared__ float smem_r[TPB / 32];
    if (lane == 0) smem_r[warp] = acc;
    __syncthreads();
    if (tid == 0) {
        float b = 0.0f;
        #pragma unroll
        for (int w = 0; w < TPB / 32; w++) b += smem_r[w];
        g_part[bid] = b;   // plain overwrite: deterministic across graph replays
    }
}

// ---------------------------------------------------------------- sum
__global__ void k_sum(int nblocks) {
    __shared__ double smem[32];
    double acc = 0.0;
    for (int i = threadIdx.x; i < nblocks; i += blockDim.x)
        acc += (double)g_part[i];
    #pragma unroll
    for (int o = 16; o > 0; o >>= 1)
        acc += __shfl_down_sync(FULL, acc, o);
    const int lane = threadIdx.x & 31;
    const int warp = threadIdx.x >> 5;
    if (lane == 0) smem[warp] = acc;
    __syncthreads();
    if (threadIdx.x == 0) {
        double s = 0.0;
        const int nw = blockDim.x / 32;
        for (int w = 0; w < nw; w++) s += smem[w];
        g_invS = (float)(1.0 / s);
    }
}

// ---------------------------------------------------------------- pass 2
__global__ void __launch_bounds__(TPB) k_pass2(const float* __restrict__ f,
                                               float* __restrict__ out, int n) {
    const int tid  = threadIdx.x;
    const int bid  = blockIdx.x;
    const int lane = tid & 31;
    const int base = bid * CHUNK_F;
    const bool interior = (bid > 0) && (base + CHUNK_F + 5 <= n);
    const float invS = g_invS;

    if (interior) {
        #pragma unroll
        for (int j = 0; j < VPT; j++) {
            const int v = base + j * (TPB * 4) + tid * 4;
            float4 c = __ldg(reinterpret_cast<const float4*>(f + v));
            float m3 = __shfl_up_sync(FULL, c.y, 1);
            float m2 = __shfl_up_sync(FULL, c.z, 1);
            float m1 = __shfl_up_sync(FULL, c.w, 1);
            float p4 = __shfl_down_sync(FULL, c.x, 1);
            float p5 = __shfl_down_sync(FULL, c.y, 1);
            if (lane == 0) {
                m3 = __ldg(f + v - 3);
                m2 = __ldg(f + v - 2);
                m1 = __ldg(f + v - 1);
            }
            if (lane == 31) {
                p4 = __ldg(f + v + 4);
                p5 = __ldg(f + v + 5);
            }
            float d0 = (m3  - c.z) * 0.2f;
            float d1 = (m2  - c.w) * 0.2f;
            float d2 = (m1  - p4 ) * 0.2f;
            float d3 = (c.x - p5 ) * 0.2f;
            float t0 = 1.0f - d0 * d0 * invS;
            float t1 = 1.0f - d1 * d1 * invS;
            float t2 = 1.0f - d2 * d2 * invS;
            float t3 = 1.0f - d3 * d3 * invS;
            float q0 = t0 * t0, q1 = t1 * t1, q2 = t2 * t2, q3 = t3 * t3;
            float4 o;
            o.x = q0 * q0 * t0 * c.x;
            o.y = q1 * q1 * t1 * c.y;
            o.z = q2 * q2 * t2 * c.z;
            o.w = q3 * q3 * t3 * c.w;
            __stcs(reinterpret_cast<float4*>(out + v), o);
        }
    } else {
        #pragma unroll
        for (int j = 0; j < VPT; j++) {
            const int v = base + j * (TPB * 4) + tid * 4;
            if (v + 3 < n) {
                float4 c = __ldg(reinterpret_cast<const float4*>(f + v));
                float m3 = (v >= 3)    ? __ldg(f + v - 3) : 0.0f;
                float m2 = (v >= 2)    ? __ldg(f + v - 2) : 0.0f;
                float m1 = (v >= 1)    ? __ldg(f + v - 1) : 0.0f;
                float p4 = (v + 4 < n) ? __ldg(f + v + 4) : 0.0f;
                float p5 = (v + 5 < n) ? __ldg(f + v + 5) : 0.0f;
                float d0 = (m3  - c.z) * 0.2f;
                float d1 = (m2  - c.w) * 0.2f;
                float d2 = (m1  - p4 ) * 0.2f;
                float d3 = (c.x - p5 ) * 0.2f;
                float c0 = (v == 0) ? 0.0f : d0 * d0 * invS;
                float t0 = 1.0f - c0;
                float t1 = 1.0f - d1 * d1 * invS;
                float t2 = 1.0f - d2 * d2 * invS;
                float t3 = 1.0f - d3 * d3 * invS;
                float q0 = t0 * t0, q1 = t1 * t1, q2 = t2 * t2, q3 = t3 * t3;
                float4 o;
                o.x = q0 * q0 * t0 * c.x;
                o.y = q1 * q1 * t1 * c.y;
                o.z = q2 * q2 * t2 * c.z;
                o.w = q3 * q3 * t3 * c.w;
                __stcs(reinterpret_cast<float4*>(out + v), o);
            } else if (v < n) {
                for (int k = v; k < n; k++) {
                    float l = (k >= 3)    ? __ldg(f + k - 3) : 0.0f;
                    float r = (k + 2 < n) ? __ldg(f + k + 2) : 0.0f;
                    float d = (l - r) * 0.2f;
                    float ch = (k == 0) ? 0.0f : d * d * invS;
                    float t = 1.0f - ch;
                    float q = t * t;
                    out[k] = q * q * t * __ldg(f + k);
                }
            }
        }
    }
}

// ---------------------------------------------------------------- launch
extern "C" void kernel_launch(void* const* d_in, const int* in_sizes, int n_in,
                              void* d_out, int out_size) {
    const float* f = (const float*)d_in[0];
    float* out = (float*)d_out;
    int n = in_sizes[0];

    int blocks = (n + CHUNK_F - 1) / CHUNK_F;
    if (blocks > MAX_BLOCKS) blocks = MAX_BLOCKS;

    k_pass1<<<blocks, TPB>>>(f, n);
    k_sum<<<1, 1024>>>(blocks);
    k_pass2<<<blocks, TPB>>>(f, out, n);
}

// round 8
// speedup vs baseline: 1.0106x; 1.0106x over previous
#include <cuda_runtime.h>
#include <cstdint>

// diff[k] = (f[k-3] - f[k+2]) / 5 with zero-padding outside [0,n)
// change[k] = diff[k]^2 for k>=1, change[0] = 0
// out[k] = (1 - change[k]/S)^5 * f[k],  S = sum(change)

#define TPB 256
#define VPT 5                              // float4 vectors per thread (batched)
#define ELEMS_PER_BLOCK (TPB * VPT * 4)    // 5120
#define MAX_BLOCKS 16384
#define FULL 0xffffffffu

__device__ float g_part[MAX_BLOCKS];
__device__ float g_invS;

// L2 evict-last policy: keep f resident in L2 across passes AND graph replays.
__device__ __forceinline__ uint64_t mk_evict_last() {
    uint64_t pol;
    asm("createpolicy.fractional.L2::evict_last.b64 %0, 1.0;" : "=l"(pol));
    return pol;
}

__device__ __forceinline__ float4 ld_el_v4(const float* p, uint64_t pol) {
    float4 r;
    asm volatile("ld.global.L2::cache_hint.v4.f32 {%0,%1,%2,%3}, [%4], %5;"
                 : "=f"(r.x), "=f"(r.y), "=f"(r.z), "=f"(r.w)
                 : "l"(p), "l"(pol));
    return r;
}

__device__ __forceinline__ float ld_el_f(const float* p, uint64_t pol) {
    float r;
    asm volatile("ld.global.L2::cache_hint.f32 %0, [%1], %2;"
                 : "=f"(r) : "l"(p), "l"(pol));
    return r;
}

// ---------------------------------------------------------------- pass 1
__global__ void __launch_bounds__(TPB, 6) k_pass1(const float* __restrict__ f, int n) {
    const int tid  = threadIdx.x;
    const int bid  = blockIdx.x;
    const int lane = tid & 31;
    const int base = bid * ELEMS_PER_BLOCK;
    const bool interior = (bid > 0) && (base + ELEMS_PER_BLOCK + 5 <= n);

    float acc = 0.0f;

    if (interior) {
        const uint64_t pol = mk_evict_last();
        // batch the 5 main loads back-to-back (deep MLP, low register cost)
        float4 c[VPT];
        #pragma unroll
        for (int j = 0; j < VPT; j++) {
            const int v = base + j * (TPB * 4) + tid * 4;
            c[j] = ld_el_v4(f + v, pol);
        }
        // halo via shuffle; edge lanes fall back to (L2-hit) loads
        #pragma unroll
        for (int j = 0; j < VPT; j++) {
            const int v = base + j * (TPB * 4) + tid * 4;
            float m3 = __shfl_up_sync(FULL, c[j].y, 1);
            float m2 = __shfl_up_sync(FULL, c[j].z, 1);
            float m1 = __shfl_up_sync(FULL, c[j].w, 1);
            float p4 = __shfl_down_sync(FULL, c[j].x, 1);
            float p5 = __shfl_down_sync(FULL, c[j].y, 1);
            if (lane == 0) {
                m3 = ld_el_f(f + v - 3, pol);
                m2 = ld_el_f(f + v - 2, pol);
                m1 = ld_el_f(f + v - 1, pol);
            }
            if (lane == 31) {
                p4 = ld_el_f(f + v + 4, pol);
                p5 = ld_el_f(f + v + 5, pol);
            }
            float d0 = (m3     - c[j].z) * 0.2f;
            float d1 = (m2     - c[j].w) * 0.2f;
            float d2 = (m1     - p4    ) * 0.2f;
            float d3 = (c[j].x - p5    ) * 0.2f;
            acc += d0 * d0 + d1 * d1 + d2 * d2 + d3 * d3;
        }
    } else {
        #pragma unroll
        for (int j = 0; j < VPT; j++) {
            const int v = base + j * (TPB * 4) + tid * 4;
            if (v + 3 < n) {
                float4 c = __ldg(reinterpret_cast<const float4*>(f + v));
                float m3 = (v >= 3)     ? __ldg(f + v - 3) : 0.0f;
                float m2 = (v >= 2)     ? __ldg(f + v - 2) : 0.0f;
                float m1 = (v >= 1)     ? __ldg(f + v - 1) : 0.0f;
                float p4 = (v + 4 < n)  ? __ldg(f + v + 4) : 0.0f;
                float p5 = (v + 5 < n)  ? __ldg(f + v + 5) : 0.0f;
                float d0 = (m3  - c.z) * 0.2f;
                float d1 = (m2  - c.w) * 0.2f;
                float d2 = (m1  - p4 ) * 0.2f;
                float d3 = (c.x - p5 ) * 0.2f;
                float c0 = (v == 0) ? 0.0f : d0 * d0;
                acc += c0 + d1 * d1 + d2 * d2 + d3 * d3;
            } else if (v < n) {
                for (int k = v; k < n; k++) {
                    float l = (k >= 3)    ? __ldg(f + k - 3) : 0.0f;
                    float r = (k + 2 < n) ? __ldg(f + k + 2) : 0.0f;
                    float d = (l - r) * 0.2f;
                    if (k != 0) acc += d * d;
                }
            }
        }
    }

    #pragma unroll
    for (int o = 16; o > 0; o >>= 1)
        acc += __shfl_down_sync(FULL, acc, o);

    __shared__ float smem[TPB / 32];
    const int warp = tid >> 5;
    if (lane == 0) smem[warp] = acc;
    __syncthreads();
    if (tid == 0) {
        float b = 0.0f;
        #pragma unroll
        for (int w = 0; w < TPB / 32; w++) b += smem[w];
        g_part[bid] = b;   // plain overwrite: deterministic across graph replays
    }
}

// ---------------------------------------------------------------- sum
__global__ void k_sum(int nblocks) {
    __shared__ double smem[32];
    double acc = 0.0;
    for (int i = threadIdx.x; i < nblocks; i += blockDim.x)
        acc += (double)g_part[i];
    #pragma unroll
    for (int o = 16; o > 0; o >>= 1)
        acc += __shfl_down_sync(FULL, acc, o);
    const int lane = threadIdx.x & 31;
    const int warp = threadIdx.x >> 5;
    if (lane == 0) smem[warp] = acc;
    __syncthreads();
    if (threadIdx.x == 0) {
        double s = 0.0;
        const int nw = blockDim.x / 32;
        for (int w = 0; w < nw; w++) s += smem[w];
        g_invS = (float)(1.0 / s);
    }
}

// ---------------------------------------------------------------- pass 2
__global__ void __launch_bounds__(TPB, 6) k_pass2(const float* __restrict__ f,
                                                  float* __restrict__ out, int n) {
    const int tid  = threadIdx.x;
    const int bid  = blockIdx.x;
    const int lane = tid & 31;
    const int base = bid * ELEMS_PER_BLOCK;
    const bool interior = (bid > 0) && (base + ELEMS_PER_BLOCK + 5 <= n);
    const float invS = g_invS;

    if (interior) {
        const uint64_t pol = mk_evict_last();
        float4 c[VPT];
        #pragma unroll
        for (int j = 0; j < VPT; j++) {
            const int v = base + j * (TPB * 4) + tid * 4;
            c[j] = ld_el_v4(f + v, pol);
        }
        #pragma unroll
        for (int j = 0; j < VPT; j++) {
            const int v = base + j * (TPB * 4) + tid * 4;
            float m3 = __shfl_up_sync(FULL, c[j].y, 1);
            float m2 = __shfl_up_sync(FULL, c[j].z, 1);
            float m1 = __shfl_up_sync(FULL, c[j].w, 1);
            float p4 = __shfl_down_sync(FULL, c[j].x, 1);
            float p5 = __shfl_down_sync(FULL, c[j].y, 1);
            if (lane == 0) {
                m3 = ld_el_f(f + v - 3, pol);
                m2 = ld_el_f(f + v - 2, pol);
                m1 = ld_el_f(f + v - 1, pol);
            }
            if (lane == 31) {
                p4 = ld_el_f(f + v + 4, pol);
                p5 = ld_el_f(f + v + 5, pol);
            }
            float d0 = (m3     - c[j].z) * 0.2f;
            float d1 = (m2     - c[j].w) * 0.2f;
            float d2 = (m1     - p4    ) * 0.2f;
            float d3 = (c[j].x - p5    ) * 0.2f;
            float t0 = 1.0f - d0 * d0 * invS;
            float t1 = 1.0f - d1 * d1 * invS;
            float t2 = 1.0f - d2 * d2 * invS;
            float t3 = 1.0f - d3 * d3 * invS;
            float q0 = t0 * t0, q1 = t1 * t1, q2 = t2 * t2, q3 = t3 * t3;
            float4 o;
            o.x = q0 * q0 * t0 * c[j].x;
            o.y = q1 * q1 * t1 * c[j].y;
            o.z = q2 * q2 * t2 * c[j].z;
            o.w = q3 * q3 * t3 * c[j].w;
            __stcs(reinterpret_cast<float4*>(out + v), o);   // evict-first stores
        }
    } else {
        #pragma unroll
        for (int j = 0; j < VPT; j++) {
            const int v = base + j * (TPB * 4) + tid * 4;
            if (v + 3 < n) {
                float4 c = __ldg(reinterpret_cast<const float4*>(f + v));
                float m3 = (v >= 3)    ? __ldg(f + v - 3) : 0.0f;
                float m2 = (v >= 2)    ? __ldg(f + v - 2) : 0.0f;
                float m1 = (v >= 1)    ? __ldg(f + v - 1) : 0.0f;
                float p4 = (v + 4 < n) ? __ldg(f + v + 4) : 0.0f;
                float p5 = (v + 5 < n) ? __ldg(f + v + 5) : 0.0f;
                float d0 = (m3  - c.z) * 0.2f;
                float d1 = (m2  - c.w) * 0.2f;
                float d2 = (m1  - p4 ) * 0.2f;
                float d3 = (c.x - p5 ) * 0.2f;
                float c0 = (v == 0) ? 0.0f : d0 * d0 * invS;
                float t0 = 1.0f - c0;
                float t1 = 1.0f - d1 * d1 * invS;
                float t2 = 1.0f - d2 * d2 * invS;
                float t3 = 1.0f - d3 * d3 * invS;
                float q0 = t0 * t0, q1 = t1 * t1, q2 = t2 * t2, q3 = t3 * t3;
                float4 o;
                o.x = q0 * q0 * t0 * c.x;
                o.y = q1 * q1 * t1 * c.y;
                o.z = q2 * q2 * t2 * c.z;
                o.w = q3 * q3 * t3 * c.w;
                __stcs(reinterpret_cast<float4*>(out + v), o);
            } else if (v < n) {
                for (int k = v; k < n; k++) {
                    float l = (k >= 3)    ? __ldg(f + k - 3) : 0.0f;
                    float r = (k + 2 < n) ? __ldg(f + k + 2) : 0.0f;
                    float d = (l - r) * 0.2f;
                    float ch = (k == 0) ? 0.0f : d * d * invS;
                    float t = 1.0f - ch;
                    float q = t * t;
                    out[k] = q * q * t * __ldg(f + k);
                }
            }
        }
    }
}

// ---------------------------------------------------------------- launch
extern "C" void kernel_launch(void* const* d_in, const int* in_sizes, int n_in,
                              void* d_out, int out_size) {
    const float* f = (const float*)d_in[0];
    float* out = (float*)d_out;
    int n = in_sizes[0];

    int blocks = (n + ELEMS_PER_BLOCK - 1) / ELEMS_PER_BLOCK;
    if (blocks > MAX_BLOCKS) blocks = MAX_BLOCKS;

    k_pass1<<<blocks, TPB>>>(f, n);
    k_sum<<<1, 1024>>>(blocks);
    k_pass2<<<blocks, TPB>>>(f, out, n);
}

// round 9
// speedup vs baseline: 1.1935x; 1.1809x over previous
#include <cuda_runtime.h>

// diff[k] = (f[k-3] - f[k+2]) / 5 with zero-padding outside [0,n)
// change[k] = diff[k]^2 for k>=1, change[0] = 0
// out[k] = (1 - change[k]/S)^5 * f[k],  S = sum(change)
//
// Single persistent kernel, block-stride super-chunks:
//   phase1 (partial sums, batched-MLP loop) -> generation-counter grid sync
//   -> phase2 (same chunks per block => L2/L1-warm reads, streaming writes).

#define TPB 256
#define VPT 5                              // float4 vectors per thread (batched)
#define EPB (TPB * VPT * 4)                // 5120 elems per super-chunk
#define GRID 888                           // 148 SMs x 6 blocks, fully resident
#define FULL 0xffffffffu

__device__ float g_part[GRID];
__device__ float g_invS;
__device__ unsigned long long g_arrive  = 0;   // monotonic across graph replays
__device__ unsigned long long g_release = 0;

__global__ void __launch_bounds__(TPB, 6) k_fused(const float* __restrict__ f,
                                                  float* __restrict__ out, int n) {
    const int tid  = threadIdx.x;
    const int lane = tid & 31;
    const int warp = tid >> 5;
    const int nchunks = (n + EPB - 1) / EPB;

    __shared__ float  s_w[TPB / 32];
    __shared__ double s_d[TPB / 32];
    __shared__ float  s_invS;
    __shared__ int    s_last;

    // ======================= phase 1: sum of change =======================
    float acc = 0.0f;
    for (int sc = blockIdx.x; sc < nchunks; sc += GRID) {
        const int base = sc * EPB;
        if (sc > 0 && base + EPB + 5 <= n) {
            // interior: batch 5 main loads (deep MLP), halo via shuffle
            float4 c[VPT];
            #pragma unroll
            for (int j = 0; j < VPT; j++) {
                const int v = base + j * (TPB * 4) + tid * 4;
                c[j] = __ldg(reinterpret_cast<const float4*>(f + v));
            }
            #pragma unroll
            for (int j = 0; j < VPT; j++) {
                const int v = base + j * (TPB * 4) + tid * 4;
                float m3 = __shfl_up_sync(FULL, c[j].y, 1);
                float m2 = __shfl_up_sync(FULL, c[j].z, 1);
                float m1 = __shfl_up_sync(FULL, c[j].w, 1);
                float p4 = __shfl_down_sync(FULL, c[j].x, 1);
                float p5 = __shfl_down_sync(FULL, c[j].y, 1);
                if (lane == 0) {
                    m3 = __ldg(f + v - 3);
                    m2 = __ldg(f + v - 2);
                    m1 = __ldg(f + v - 1);
                }
                if (lane == 31) {
                    p4 = __ldg(f + v + 4);
                    p5 = __ldg(f + v + 5);
                }
                float d0 = (m3     - c[j].z) * 0.2f;
                float d1 = (m2     - c[j].w) * 0.2f;
                float d2 = (m1     - p4    ) * 0.2f;
                float d3 = (c[j].x - p5    ) * 0.2f;
                acc += d0 * d0 + d1 * d1 + d2 * d2 + d3 * d3;
            }
        } else {
            #pragma unroll
            for (int j = 0; j < VPT; j++) {
                const int v = base + j * (TPB * 4) + tid * 4;
                if (v + 3 < n) {
                    float4 c = __ldg(reinterpret_cast<const float4*>(f + v));
                    float m3 = (v >= 3)     ? __ldg(f + v - 3) : 0.0f;
                    float m2 = (v >= 2)     ? __ldg(f + v - 2) : 0.0f;
                    float m1 = (v >= 1)     ? __ldg(f + v - 1) : 0.0f;
                    float p4 = (v + 4 < n)  ? __ldg(f + v + 4) : 0.0f;
                    float p5 = (v + 5 < n)  ? __ldg(f + v + 5) : 0.0f;
                    float d0 = (m3  - c.z) * 0.2f;
                    float d1 = (m2  - c.w) * 0.2f;
                    float d2 = (m1  - p4 ) * 0.2f;
                    float d3 = (c.x - p5 ) * 0.2f;
                    float c0 = (v == 0) ? 0.0f : d0 * d0;
                    acc += c0 + d1 * d1 + d2 * d2 + d3 * d3;
                } else if (v < n) {
                    for (int k = v; k < n; k++) {
                        float l = (k >= 3)    ? __ldg(f + k - 3) : 0.0f;
                        float r = (k + 2 < n) ? __ldg(f + k + 2) : 0.0f;
                        float d = (l - r) * 0.2f;
                        if (k != 0) acc += d * d;
                    }
                }
            }
        }
    }

    #pragma unroll
    for (int o = 16; o > 0; o >>= 1)
        acc += __shfl_down_sync(FULL, acc, o);
    if (lane == 0) s_w[warp] = acc;
    __syncthreads();

    // ======================= grid sync (generation counters) ==============
    if (tid == 0) {
        float b = 0.0f;
        #pragma unroll
        for (int w = 0; w < TPB / 32; w++) b += s_w[w];
        g_part[blockIdx.x] = b;
        __threadfence();
        unsigned long long ticket = atomicAdd(&g_arrive, 1ULL);
        unsigned long long gen = ticket / (unsigned long long)GRID;
        int last = ((int)(ticket % (unsigned long long)GRID) == GRID - 1);
        s_last = last;
        if (!last) {
            while (*((volatile unsigned long long*)&g_release) < gen + 1ULL) {
                __nanosleep(32);
            }
            __threadfence();
            s_invS = *((volatile float*)&g_invS);
        }
    }
    __syncthreads();

    if (s_last) {   // block-uniform
        __threadfence();
        double a = 0.0;
        for (int i = tid; i < GRID; i += TPB)
            a += (double)g_part[i];
        #pragma unroll
        for (int o = 16; o > 0; o >>= 1)
            a += __shfl_down_sync(FULL, a, o);
        if (lane == 0) s_d[warp] = a;
        __syncthreads();
        if (tid == 0) {
            double s = 0.0;
            #pragma unroll
            for (int w = 0; w < TPB / 32; w++) s += s_d[w];
            float inv = (float)(1.0 / s);
            s_invS = inv;
            *((volatile float*)&g_invS) = inv;
            __threadfence();
            atomicAdd(&g_release, 1ULL);
        }
        __syncthreads();
    }

    const float invS = s_invS;

    // ======================= phase 2: scale + write ========================
    // Same block-stride chunks as phase 1 => reads are L2/L1 warm.
    for (int sc = blockIdx.x; sc < nchunks; sc += GRID) {
        const int base = sc * EPB;
        if (sc > 0 && base + EPB + 5 <= n) {
            float4 c[VPT];
            #pragma unroll
            for (int j = 0; j < VPT; j++) {
                const int v = base + j * (TPB * 4) + tid * 4;
                c[j] = __ldg(reinterpret_cast<const float4*>(f + v));
            }
            #pragma unroll
            for (int j = 0; j < VPT; j++) {
                const int v = base + j * (TPB * 4) + tid * 4;
                float m3 = __shfl_up_sync(FULL, c[j].y, 1);
                float m2 = __shfl_up_sync(FULL, c[j].z, 1);
                float m1 = __shfl_up_sync(FULL, c[j].w, 1);
                float p4 = __shfl_down_sync(FULL, c[j].x, 1);
                float p5 = __shfl_down_sync(FULL, c[j].y, 1);
                if (lane == 0) {
                    m3 = __ldg(f + v - 3);
                    m2 = __ldg(f + v - 2);
                    m1 = __ldg(f + v - 1);
                }
                if (lane == 31) {
                    p4 = __ldg(f + v + 4);
                    p5 = __ldg(f + v + 5);
                }
                float d0 = (m3     - c[j].z) * 0.2f;
                float d1 = (m2     - c[j].w) * 0.2f;
                float d2 = (m1     - p4    ) * 0.2f;
                float d3 = (c[j].x - p5    ) * 0.2f;
                float t0 = 1.0f - d0 * d0 * invS;
                float t1 = 1.0f - d1 * d1 * invS;
                float t2 = 1.0f - d2 * d2 * invS;
                float t3 = 1.0f - d3 * d3 * invS;
                float q0 = t0 * t0, q1 = t1 * t1, q2 = t2 * t2, q3 = t3 * t3;
                float4 o;
                o.x = q0 * q0 * t0 * c[j].x;
                o.y = q1 * q1 * t1 * c[j].y;
                o.z = q2 * q2 * t2 * c[j].z;
                o.w = q3 * q3 * t3 * c[j].w;
                __stcs(reinterpret_cast<float4*>(out + v), o);
            }
        } else {
            #pragma unroll
            for (int j = 0; j < VPT; j++) {
                const int v = base + j * (TPB * 4) + tid * 4;
                if (v + 3 < n) {
                    float4 c = __ldg(reinterpret_cast<const float4*>(f + v));
                    float m3 = (v >= 3)    ? __ldg(f + v - 3) : 0.0f;
                    float m2 = (v >= 2)    ? __ldg(f + v - 2) : 0.0f;
                    float m1 = (v >= 1)    ? __ldg(f + v - 1) : 0.0f;
                    float p4 = (v + 4 < n) ? __ldg(f + v + 4) : 0.0f;
                    float p5 = (v + 5 < n) ? __ldg(f + v + 5) : 0.0f;
                    float d0 = (m3  - c.z) * 0.2f;
                    float d1 = (m2  - c.w) * 0.2f;
                    float d2 = (m1  - p4 ) * 0.2f;
                    float d3 = (c.x - p5 ) * 0.2f;
                    float c0 = (v == 0) ? 0.0f : d0 * d0 * invS;
                    float t0 = 1.0f - c0;
                    float t1 = 1.0f - d1 * d1 * invS;
                    float t2 = 1.0f - d2 * d2 * invS;
                    float t3 = 1.0f - d3 * d3 * invS;
                    float q0 = t0 * t0, q1 = t1 * t1, q2 = t2 * t2, q3 = t3 * t3;
                    float4 o;
                    o.x = q0 * q0 * t0 * c.x;
                    o.y = q1 * q1 * t1 * c.y;
                    o.z = q2 * q2 * t2 * c.z;
                    o.w = q3 * q3 * t3 * c.w;
                    __stcs(reinterpret_cast<float4*>(out + v), o);
                } else if (v < n) {
                    for (int k = v; k < n; k++) {
                        float l = (k >= 3)    ? __ldg(f + k - 3) : 0.0f;
                        float r = (k + 2 < n) ? __ldg(f + k + 2) : 0.0f;
                        float d = (l - r) * 0.2f;
                        float ch = (k == 0) ? 0.0f : d * d * invS;
                        float t = 1.0f - ch;
                        float q = t * t;
                        out[k] = q * q * t * __ldg(f + k);
                    }
                }
            }
        }
    }
}

// ---------------------------------------------------------------- launch
extern "C" void kernel_launch(void* const* d_in, const int* in_sizes, int n_in,
                              void* d_out, int out_size) {
    const float* f = (const float*)d_in[0];
    float* out = (float*)d_out;
    int n = in_sizes[0];

    k_fused<<<GRID, TPB>>>(f, out, n);
}